// round 10
// baseline (speedup 1.0000x reference)
#include <cuda_runtime.h>
#include <cuda_bf16.h>
#include <cstdint>
#include <math.h>

// ---------------- problem constants ----------------
#define BATCH   32
#define SEQ     1024
#define CH      384          // C == H == 384
#define KTOT    1152         // 3 * 384
#define MAXOUT  3072
#define ROWS    (BATCH*SEQ)  // 32768

// GEMM tiling: TM=64 rows per CTA, 256 threads, 2 CTAs/SM
#define TM      64
#define KC      32
#define NITER   (KTOT/KC)    // 36
#define APAD    40           // halves per A smem row (32 + 8 pad) -> 80B stride, LDSM conflict-free
#define BPAD    40
#define NTHR    256
#define NSTAGE  2
#define NTILES  512          // conv tiles per layer (32768/64)
#define TPB     16           // tiles per batch (1024/64)

// smem layout (bytes)
#define A_BYTES (TM*APAD*2)                    // 5120
#define B_BYTES (CH*BPAD*2)                    // 30720
#define OFF_B     (NSTAGE*A_BYTES)             // 10240
#define OFF_PARAM (OFF_B + NSTAGE*B_BYTES)     // 71680
#define OFF_PART  (OFF_PARAM + 4*CH*4)         // 77824
#define OFF_MEAN  (OFF_PART + TM*8*4)          // 79872
#define OFF_RSTD  (OFF_MEAN + TM*4)            // 80128
#define SMEM_TOTAL (OFF_RSTD + TM*4)           // 80384

// ---------------- device scratch (no allocations allowed) ----------------
__device__ __nv_bfloat16 g_xbf[ROWS*CH];     // bf16 copy of x
__device__ __nv_bfloat16 g_h1 [ROWS*CH];     // layer-1 output (bf16)
__device__ __nv_bfloat16 g_w1T[CH*KTOT];     // w1 transposed: [o][k*CH+c]
__device__ __nv_bfloat16 g_w2T[CH*KTOT];
__device__ int           g_cum[ROWS];        // per-batch cumsum of durations
__device__ int           g_flag[NTILES];     // layer-1 tile completion flags

// ---------------- merged prep kernel: cvt_x + cvt_w1 + cvt_w2 + flag reset ----------------
#define N2     (ROWS*CH/2)
#define WN     (CH*KTOT)
#define PREP_TOTAL (N2 + 2*WN + NTILES)

__global__ void prep_kernel(const float* __restrict__ x,
                            const float* __restrict__ w1,
                            const float* __restrict__ w2) {
    int i = blockIdx.x * blockDim.x + threadIdx.x;
    if (i < N2) {
        float2 v = reinterpret_cast<const float2*>(x)[i];
        reinterpret_cast<__nv_bfloat162*>(g_xbf)[i] = __floats2bfloat162_rn(v.x, v.y);
    } else if (i < N2 + 2*WN) {
        int j = i - N2;
        const float* w = (j < WN) ? w1 : w2;
        __nv_bfloat16* dst = (j < WN) ? g_w1T : g_w2T;
        if (j >= WN) j -= WN;
        int o  = j / KTOT;
        int kc = j - o * KTOT;
        dst[(size_t)o * KTOT + kc] = __float2bfloat16(w[(size_t)kc * CH + o]);
    } else if (i < PREP_TOTAL) {
        g_flag[i - N2 - 2*WN] = 0;
    }
}

__global__ void cumsum_kernel(const int* __restrict__ dur) {
    __shared__ int s[SEQ];
    int b = blockIdx.x, t = threadIdx.x;
    s[t] = dur[b * SEQ + t];
    __syncthreads();
    #pragma unroll
    for (int off = 1; off < SEQ; off <<= 1) {
        int v = (t >= off) ? s[t - off] : 0;
        __syncthreads();
        s[t] += v;
        __syncthreads();
    }
    g_cum[b * SEQ + t] = s[t];
}

// ---------------- ptx helpers ----------------
__device__ __forceinline__ void mma16816(float* c, const uint32_t* a, uint32_t b0, uint32_t b1) {
    asm volatile(
        "mma.sync.aligned.m16n8k16.row.col.f32.bf16.bf16.f32 "
        "{%0,%1,%2,%3}, {%4,%5,%6,%7}, {%8,%9}, {%0,%1,%2,%3};\n"
        : "+f"(c[0]), "+f"(c[1]), "+f"(c[2]), "+f"(c[3])
        : "r"(a[0]), "r"(a[1]), "r"(a[2]), "r"(a[3]), "r"(b0), "r"(b1));
}
__device__ __forceinline__ void ldsm4(uint32_t* r, uint32_t addr) {
    asm volatile("ldmatrix.sync.aligned.m8n8.x4.shared.b16 {%0,%1,%2,%3}, [%4];\n"
                 : "=r"(r[0]), "=r"(r[1]), "=r"(r[2]), "=r"(r[3]) : "r"(addr));
}
__device__ __forceinline__ void cp_async16(uint32_t dst, const void* gptr, int sz) {
    asm volatile("cp.async.cg.shared.global [%0], [%1], 16, %2;\n" :: "r"(dst), "l"(gptr), "r"(sz));
}
__device__ __forceinline__ void cp_async16(uint32_t dst, const void* gptr) {
    asm volatile("cp.async.cg.shared.global [%0], [%1], 16;\n" :: "r"(dst), "l"(gptr));
}
__device__ __forceinline__ void cp_commit() { asm volatile("cp.async.commit_group;\n"); }
__device__ __forceinline__ void cp_wait1()  { asm volatile("cp.async.wait_group 1;\n"); }
__device__ __forceinline__ void cp_wait0()  { asm volatile("cp.async.wait_group 0;\n"); }

// ---------------- merged dual-layer conv kernel ----------------
// Blocks 0..511:    layer 1 tiles -> g_h1 + completion flag
// Blocks 512..1023: layer 2 tiles (spin on <=3 neighbor flags) -> pred
__global__ __launch_bounds__(NTHR, 2)
void conv_ln_kernel(const float* __restrict__ b1v,
                    const float* __restrict__ g1v,
                    const float* __restrict__ be1v,
                    const float* __restrict__ b2v,
                    const float* __restrict__ g2v,
                    const float* __restrict__ be2v,
                    const float* __restrict__ wl,
                    const float* __restrict__ bl,
                    float* __restrict__ pred)
{
    extern __shared__ char smem[];
    const uint32_t smem_base = (uint32_t)__cvta_generic_to_shared(smem);
    float* sBias  = (float*)(smem + OFF_PARAM);
    float* sGamma = sBias  + CH;
    float* sBeta  = sGamma + CH;
    float* sWl    = sBeta  + CH;
    float* sPart  = (float*)(smem + OFF_PART);   // [TM][8]
    float* sMean  = (float*)(smem + OFF_MEAN);   // [TM]
    float* sRstd  = (float*)(smem + OFF_RSTD);   // [TM]

    const bool PRED = blockIdx.x >= NTILES;
    const int  bidx = PRED ? (blockIdx.x - NTILES) : blockIdx.x;   // tile 0..511

    const __nv_bfloat16* Ain = PRED ? g_h1  : g_xbf;
    const __nv_bfloat16* WT  = PRED ? g_w2T : g_w1T;
    const float* bias  = PRED ? b2v  : b1v;
    const float* gamma = PRED ? g2v  : g1v;
    const float* beta  = PRED ? be2v : be1v;

    const int tid  = threadIdx.x;
    const int b    = bidx >> 4;             // 16 tiles per batch
    const int s0   = (bidx & (TPB - 1)) * TM;
    const size_t rowBase = (size_t)b * SEQ;

    for (int i = tid; i < CH; i += NTHR) {
        sBias[i]  = bias[i];
        sGamma[i] = gamma[i];
        sBeta[i]  = beta[i];
        sWl[i]    = PRED ? wl[i] : 0.0f;
    }

    // ---- layer-2 blocks: wait for the layer-1 tiles whose rows we read ----
    if (PRED) {
        if (tid == 0) {
            int i = bidx & (TPB - 1), base = bidx & ~(TPB - 1);
            int lo = base + max(i - 1, 0), hi = base + min(i + 1, TPB - 1);
            for (int d = lo; d <= hi; d++)
                while (*(volatile int*)&g_flag[d] == 0) {}
        }
        __threadfence();
        __syncthreads();
    }

    // ---- tile loader (cp.async, padded layout) ----
    auto load_tile = [&](int ci, int st) {
        const int k  = ci / 12;             // conv tap 0..2
        const int c0 = (ci % 12) * KC;      // channel base within tap
        const uint32_t Ad = smem_base + st * A_BYTES;
        const uint32_t Bd = smem_base + OFF_B + st * B_BYTES;
        {   // A: 64 rows x 64B = 256 x 16B reqs, 1 per thread
            int r = tid >> 2, seg = tid & 3;
            int gs = s0 + r + k - 1;                // batch-local padded row
            bool ok = (unsigned)gs < (unsigned)SEQ;
            const void* src = ok ? (const void*)(Ain + (rowBase + gs) * CH + c0 + seg * 8)
                                 : (const void*)Ain;
            cp_async16(Ad + (r * APAD + seg * 8) * 2, src, ok ? 16 : 0);
        }
        // B: 384 rows x 64B = 1536 reqs, 6 per thread
        #pragma unroll
        for (int e = 0; e < 6; e++) {
            int j = tid + e * NTHR;
            int n = j >> 2, seg = j & 3;
            cp_async16(Bd + (n * BPAD + seg * 8) * 2,
                       WT + (size_t)n * KTOT + ci * KC + seg * 8);
        }
    };

    const int wid = tid >> 5, lane = tid & 31;
    const int wm = wid >> 2, wn = wid & 3;   // 2x4 warp grid; warp tile 32(M) x 96(N)

    const int aRow = wm * 32 + (lane & 7) + ((lane >> 3) & 1) * 8;
    const int aCol = (lane >> 4) * 8;                    // halves
    const uint32_t aBase = (uint32_t)((aRow * APAD + aCol) * 2);
    const int bRow = wn * 96 + (lane & 7) + ((lane >> 4) & 1) * 8;
    const int bCol = ((lane >> 3) & 1) * 8;              // halves
    const uint32_t bBase = (uint32_t)((bRow * BPAD + bCol) * 2);

    float c[2][12][4];
    #pragma unroll
    for (int mt = 0; mt < 2; mt++)
        #pragma unroll
        for (int nt = 0; nt < 12; nt++)
            #pragma unroll
            for (int i = 0; i < 4; i++) c[mt][nt][i] = 0.0f;

    load_tile(0, 0); cp_commit();
    load_tile(1, 1); cp_commit();

    for (int ci = 0; ci < NITER; ci++) {
        const int st = ci & 1;
        if (ci < NITER - 1) cp_wait1(); else cp_wait0();
        __syncthreads();

        const uint32_t Asb = smem_base + st * A_BYTES + aBase;
        const uint32_t Bsb = smem_base + OFF_B + st * B_BYTES + bBase;
        #pragma unroll
        for (int ks = 0; ks < 2; ks++) {
            uint32_t a[2][4];
            ldsm4(a[0], Asb + ks * 32);                       // rows wm*32 +  0..15
            ldsm4(a[1], Asb + 16 * APAD * 2 + ks * 32);       // rows wm*32 + 16..31
            #pragma unroll
            for (int np = 0; np < 6; np++) {
                uint32_t bb[4];                               // 2 n8 fragments
                ldsm4(bb, Bsb + np * 16 * BPAD * 2 + ks * 32);
                mma16816(c[0][2*np  ], a[0], bb[0], bb[1]);
                mma16816(c[1][2*np  ], a[1], bb[0], bb[1]);
                mma16816(c[0][2*np+1], a[0], bb[2], bb[3]);
                mma16816(c[1][2*np+1], a[1], bb[2], bb[3]);
            }
        }
        __syncthreads();                                      // stage st fully consumed
        if (ci + 2 < NITER) { load_tile(ci + 2, st); cp_commit(); }
    }
    __syncthreads();

    // ---- epilogue: +bias, LayerNorm stats ----
    const int g = lane >> 2, tg = lane & 3;
    float psum[2][2] = {{0,0},{0,0}}, psq[2][2] = {{0,0},{0,0}};
    #pragma unroll
    for (int mt = 0; mt < 2; mt++)
        #pragma unroll
        for (int nt = 0; nt < 12; nt++) {
            int col0 = wn * 96 + nt * 8 + tg * 2;
            float bb0 = sBias[col0], bb1 = sBias[col0 + 1];
            c[mt][nt][0] += bb0; c[mt][nt][1] += bb1;
            c[mt][nt][2] += bb0; c[mt][nt][3] += bb1;
            psum[mt][0] += c[mt][nt][0] + c[mt][nt][1];
            psq [mt][0] += c[mt][nt][0]*c[mt][nt][0] + c[mt][nt][1]*c[mt][nt][1];
            psum[mt][1] += c[mt][nt][2] + c[mt][nt][3];
            psq [mt][1] += c[mt][nt][2]*c[mt][nt][2] + c[mt][nt][3]*c[mt][nt][3];
        }
    #pragma unroll
    for (int mt = 0; mt < 2; mt++)
        #pragma unroll
        for (int hi = 0; hi < 2; hi++) {
            float s = psum[mt][hi], q = psq[mt][hi];
            s += __shfl_xor_sync(0xffffffffu, s, 1); s += __shfl_xor_sync(0xffffffffu, s, 2);
            q += __shfl_xor_sync(0xffffffffu, q, 1); q += __shfl_xor_sync(0xffffffffu, q, 2);
            if (tg == 0) {
                int r = wm * 32 + mt * 16 + g + 8 * hi;
                sPart[r * 8 + wn] = s;
                sPart[r * 8 + 4 + wn] = q;
            }
        }
    __syncthreads();
    if (tid < TM) {
        float s = sPart[tid*8+0] + sPart[tid*8+1] + sPart[tid*8+2] + sPart[tid*8+3];
        float q = sPart[tid*8+4] + sPart[tid*8+5] + sPart[tid*8+6] + sPart[tid*8+7];
        float mean = s * (1.0f / CH);
        float var  = q * (1.0f / CH) - mean * mean;
        sMean[tid] = mean;
        sRstd[tid] = rsqrtf(var + 1e-5f);
    }
    __syncthreads();

    // ---- normalize + relu; store bf16 OR fused linear+exp ----
    float pd[2][2] = {{0,0},{0,0}};
    #pragma unroll
    for (int mt = 0; mt < 2; mt++) {
        int r0 = wm * 32 + mt * 16 + g;
        float m0 = sMean[r0],   rs0 = sRstd[r0];
        float m1 = sMean[r0+8], rs1 = sRstd[r0+8];
        #pragma unroll
        for (int nt = 0; nt < 12; nt++) {
            int col0 = wn * 96 + nt * 8 + tg * 2;
            float ga0 = sGamma[col0], ga1 = sGamma[col0+1];
            float be0 = sBeta[col0],  be1 = sBeta[col0+1];
            float v0 = fmaxf(0.f, (c[mt][nt][0] - m0) * rs0 * ga0 + be0);
            float v1 = fmaxf(0.f, (c[mt][nt][1] - m0) * rs0 * ga1 + be1);
            float v2 = fmaxf(0.f, (c[mt][nt][2] - m1) * rs1 * ga0 + be0);
            float v3 = fmaxf(0.f, (c[mt][nt][3] - m1) * rs1 * ga1 + be1);
            if (!PRED) {
                size_t base0 = (rowBase + s0 + r0) * CH + col0;
                *(__nv_bfloat162*)(g_h1 + base0)          = __floats2bfloat162_rn(v0, v1);
                *(__nv_bfloat162*)(g_h1 + base0 + 8 * CH) = __floats2bfloat162_rn(v2, v3);
            } else {
                float w0 = sWl[col0], w1v = sWl[col0 + 1];
                pd[mt][0] += v0 * w0 + v1 * w1v;
                pd[mt][1] += v2 * w0 + v3 * w1v;
            }
        }
    }
    if (!PRED) {
        // publish h1 tile: order stores before flag (release)
        __syncthreads();
        __threadfence();
        if (tid == 0) *(volatile int*)&g_flag[bidx] = 1;
    } else {
        #pragma unroll
        for (int mt = 0; mt < 2; mt++)
            #pragma unroll
            for (int hi = 0; hi < 2; hi++) {
                float s = pd[mt][hi];
                s += __shfl_xor_sync(0xffffffffu, s, 1);
                s += __shfl_xor_sync(0xffffffffu, s, 2);
                if (tg == 0) {
                    int r = wm * 32 + mt * 16 + g + 8 * hi;
                    sPart[r * 8 + wn] = s;
                }
            }
        __syncthreads();
        if (tid < TM) {
            float s = sPart[tid*8+0] + sPart[tid*8+1] + sPart[tid*8+2] + sPart[tid*8+3];
            pred[rowBase + s0 + tid] = expf(s + bl[0]);
        }
    }
}

// ---------------- length regulation (exact gather of fp32 x) ----------------
__global__ void gather_kernel(const float* __restrict__ x, float* __restrict__ out) {
    __shared__ int sc[SEQ];
    int b = blockIdx.y;
    for (int i = threadIdx.x; i < SEQ; i += blockDim.x) sc[i] = g_cum[b * SEQ + i];
    __syncthreads();

    int warp = threadIdx.x >> 5, lane = threadIdx.x & 31;
    int t = blockIdx.x * 8 + warp;            // 0..3071
    int total = sc[SEQ - 1];
    bool valid = t < total;
    int lo = 0, hi = SEQ;
    while (lo < hi) { int mid = (lo + hi) >> 1; if (sc[mid] <= t) lo = mid + 1; else hi = mid; }
    int src = min(lo, SEQ - 1);

    const float4* xp = (const float4*)(x + ((size_t)b * SEQ + src) * CH);
    float4* op = (float4*)(out + ((size_t)b * MAXOUT + t) * CH);
    #pragma unroll
    for (int i = 0; i < 3; i++) {
        float4 v = valid ? xp[lane + 32 * i] : make_float4(0.f, 0.f, 0.f, 0.f);
        op[lane + 32 * i] = v;
    }
}

// ---------------- launch ----------------
extern "C" void kernel_launch(void* const* d_in, const int* in_sizes, int n_in,
                              void* d_out, int out_size) {
    const float* x     = (const float*)d_in[0];
    const int*   dur   = (const int*)  d_in[1];
    const float* w1    = (const float*)d_in[2];
    const float* b1    = (const float*)d_in[3];
    const float* g1    = (const float*)d_in[4];
    const float* beta1 = (const float*)d_in[5];
    const float* w2    = (const float*)d_in[6];
    const float* b2    = (const float*)d_in[7];
    const float* g2    = (const float*)d_in[8];
    const float* beta2 = (const float*)d_in[9];
    const float* wl    = (const float*)d_in[10];
    const float* bl    = (const float*)d_in[11];

    float* res  = (float*)d_out;
    float* pred = res + (size_t)BATCH * MAXOUT * CH;

    static cudaStream_t s_aux = nullptr;
    static cudaEvent_t  ev_fork = nullptr, ev_join = nullptr;
    static bool s_init = false;
    if (!s_init) {
        cudaStreamCreateWithFlags(&s_aux, cudaStreamNonBlocking);
        cudaEventCreateWithFlags(&ev_fork, cudaEventDisableTiming);
        cudaEventCreateWithFlags(&ev_join, cudaEventDisableTiming);
        cudaFuncSetAttribute(conv_ln_kernel, cudaFuncAttributeMaxDynamicSharedMemorySize, SMEM_TOTAL);
        s_init = true;
    }

    // ---- fork: aux branch = cumsum -> gather (memory-bound, independent of convs) ----
    cudaEventRecord(ev_fork, 0);
    cudaStreamWaitEvent(s_aux, ev_fork, 0);
    cumsum_kernel<<<BATCH, SEQ, 0, s_aux>>>(dur);
    gather_kernel<<<dim3(MAXOUT / 8, BATCH), 256, 0, s_aux>>>(x, res);
    cudaEventRecord(ev_join, s_aux);

    // ---- main branch: merged prep, then dual-layer pipelined conv (2 CTAs/SM) ----
    prep_kernel<<<(PREP_TOTAL + 255) / 256, 256>>>(x, w1, w2);
    conv_ln_kernel<<<2 * NTILES, NTHR, SMEM_TOTAL>>>(b1, g1, beta1, b2, g2, beta2, wl, bl, pred);

    // ---- join ----
    cudaStreamWaitEvent(0, ev_join, 0);
}

// round 11
// speedup vs baseline: 1.0395x; 1.0395x over previous
#include <cuda_runtime.h>
#include <cuda_bf16.h>
#include <cstdint>
#include <math.h>

// ---------------- problem constants ----------------
#define BATCH   32
#define SEQ     1024
#define CH      384          // C == H == 384
#define KTOT    1152         // 3 * 384
#define MAXOUT  3072
#define ROWS    (BATCH*SEQ)  // 32768

// GEMM tiling: TM=128 rows per CTA, 512 threads, KC=64, 3 stages
#define TM      128
#define KC      64
#define NITER   (KTOT/KC)    // 18
#define APAD    72           // halves per smem row (64 + 8 pad) -> 144B stride, LDSM conflict-free
#define NTHR    512
#define NSTAGE  3
#define NTILES  256          // conv tiles per layer
#define TPB     8            // tiles per batch (1024/128)

// smem layout (bytes)
#define A_BYTES (TM*APAD*2)                    // 18432
#define B_BYTES (CH*APAD*2)                    // 55296
#define STAGE_BYTES (A_BYTES+B_BYTES)          // 73728
#define OFF_PARAM (NSTAGE*STAGE_BYTES)         // 221184
#define SMEM_TOTAL (OFF_PARAM + 4*CH*4)        // 227328  (max 232448)

// ---------------- device scratch (no allocations allowed) ----------------
__device__ __nv_bfloat16 g_xbf[ROWS*CH];     // bf16 copy of x
__device__ __nv_bfloat16 g_h1 [ROWS*CH];     // layer-1 output (bf16)
__device__ __nv_bfloat16 g_w1T[CH*KTOT];     // w1 transposed: [o][k*CH+c]
__device__ __nv_bfloat16 g_w2T[CH*KTOT];
__device__ int           g_cum[ROWS];        // per-batch cumsum of durations
__device__ int           g_flag[NTILES];     // layer-1 tile completion flags

// ---------------- merged prep kernel: cvt_x + cvt_w1 + cvt_w2 + flag reset ----------------
#define N2     (ROWS*CH/2)
#define WN     (CH*KTOT)
#define PREP_TOTAL (N2 + 2*WN + NTILES)

__global__ void prep_kernel(const float* __restrict__ x,
                            const float* __restrict__ w1,
                            const float* __restrict__ w2) {
    int i = blockIdx.x * blockDim.x + threadIdx.x;
    if (i < N2) {
        float2 v = reinterpret_cast<const float2*>(x)[i];
        reinterpret_cast<__nv_bfloat162*>(g_xbf)[i] = __floats2bfloat162_rn(v.x, v.y);
    } else if (i < N2 + 2*WN) {
        int j = i - N2;
        const float* w = (j < WN) ? w1 : w2;
        __nv_bfloat16* dst = (j < WN) ? g_w1T : g_w2T;
        if (j >= WN) j -= WN;
        int o  = j / KTOT;
        int kc = j - o * KTOT;
        dst[(size_t)o * KTOT + kc] = __float2bfloat16(w[(size_t)kc * CH + o]);
    } else if (i < PREP_TOTAL) {
        g_flag[i - N2 - 2*WN] = 0;
    }
}

__global__ void cumsum_kernel(const int* __restrict__ dur) {
    __shared__ int s[SEQ];
    int b = blockIdx.x, t = threadIdx.x;
    s[t] = dur[b * SEQ + t];
    __syncthreads();
    #pragma unroll
    for (int off = 1; off < SEQ; off <<= 1) {
        int v = (t >= off) ? s[t - off] : 0;
        __syncthreads();
        s[t] += v;
        __syncthreads();
    }
    g_cum[b * SEQ + t] = s[t];
}

// ---------------- ptx helpers ----------------
__device__ __forceinline__ void mma16816(float* c, const uint32_t* a, uint32_t b0, uint32_t b1) {
    asm volatile(
        "mma.sync.aligned.m16n8k16.row.col.f32.bf16.bf16.f32 "
        "{%0,%1,%2,%3}, {%4,%5,%6,%7}, {%8,%9}, {%0,%1,%2,%3};\n"
        : "+f"(c[0]), "+f"(c[1]), "+f"(c[2]), "+f"(c[3])
        : "r"(a[0]), "r"(a[1]), "r"(a[2]), "r"(a[3]), "r"(b0), "r"(b1));
}
__device__ __forceinline__ void ldsm4(uint32_t* r, uint32_t addr) {
    asm volatile("ldmatrix.sync.aligned.m8n8.x4.shared.b16 {%0,%1,%2,%3}, [%4];\n"
                 : "=r"(r[0]), "=r"(r[1]), "=r"(r[2]), "=r"(r[3]) : "r"(addr));
}
__device__ __forceinline__ void cp_async16(uint32_t dst, const void* gptr, int sz) {
    asm volatile("cp.async.cg.shared.global [%0], [%1], 16, %2;\n" :: "r"(dst), "l"(gptr), "r"(sz));
}
__device__ __forceinline__ void cp_async16(uint32_t dst, const void* gptr) {
    asm volatile("cp.async.cg.shared.global [%0], [%1], 16;\n" :: "r"(dst), "l"(gptr));
}
__device__ __forceinline__ void cp_commit() { asm volatile("cp.async.commit_group;\n"); }
__device__ __forceinline__ void cp_wait1()  { asm volatile("cp.async.wait_group 1;\n"); }
__device__ __forceinline__ void cp_wait0()  { asm volatile("cp.async.wait_group 0;\n"); }

// ---------------- merged dual-layer conv kernel ----------------
// Blocks 0..255:   layer 1 tiles -> g_h1 + completion flag
// Blocks 256..511: layer 2 tiles (spin on <=3 neighbor flags) -> pred
__global__ __launch_bounds__(NTHR, 1)
void conv_ln_kernel(const float* __restrict__ b1v,
                    const float* __restrict__ g1v,
                    const float* __restrict__ be1v,
                    const float* __restrict__ b2v,
                    const float* __restrict__ g2v,
                    const float* __restrict__ be2v,
                    const float* __restrict__ wl,
                    const float* __restrict__ bl,
                    float* __restrict__ pred)
{
    extern __shared__ char smem[];
    const uint32_t smem_base = (uint32_t)__cvta_generic_to_shared(smem);
    float* sBias  = (float*)(smem + OFF_PARAM);
    float* sGamma = sBias  + CH;
    float* sBeta  = sGamma + CH;
    float* sWl    = sBeta  + CH;
    // epilogue scratch overlays stage-0 tile memory (dead after mainloop)
    float* sPart  = (float*)smem;                 // [TM][8]
    float* sMean  = (float*)(smem + TM*8*4);      // [TM]
    float* sRstd  = (float*)(smem + TM*8*4 + TM*4);

    const bool PRED = blockIdx.x >= NTILES;
    const int  bidx = PRED ? (blockIdx.x - NTILES) : blockIdx.x;   // tile 0..255

    const __nv_bfloat16* Ain = PRED ? g_h1  : g_xbf;
    const __nv_bfloat16* WT  = PRED ? g_w2T : g_w1T;
    const float* bias  = PRED ? b2v  : b1v;
    const float* gamma = PRED ? g2v  : g1v;
    const float* beta  = PRED ? be2v : be1v;

    const int tid  = threadIdx.x;
    const int b    = bidx >> 3;             // 8 tiles per batch (1024/128)
    const int s0   = (bidx & (TPB - 1)) * TM;
    const size_t rowBase = (size_t)b * SEQ;

    if (tid < CH) {
        sBias[tid]  = bias[tid];
        sGamma[tid] = gamma[tid];
        sBeta[tid]  = beta[tid];
        sWl[tid]    = PRED ? wl[tid] : 0.0f;
    }

    // ---- layer-2 blocks: wait for the layer-1 tiles whose rows we read ----
    if (PRED) {
        if (tid == 0) {
            int i = bidx & (TPB - 1), base = bidx & ~(TPB - 1);
            int lo = base + max(i - 1, 0), hi = base + min(i + 1, TPB - 1);
            for (int d = lo; d <= hi; d++)
                while (*(volatile int*)&g_flag[d] == 0) {}
        }
        __threadfence();
        __syncthreads();
    }

    // ---- tile loader (cp.async, padded layout), KC=64 -> 128B per row ----
    auto load_tile = [&](int ci, int st) {
        const int tap = ci / 6;             // conv tap 0..2
        const int c0  = (ci % 6) * KC;      // channel base within tap
        const uint32_t Ad = smem_base + st * STAGE_BYTES;
        const uint32_t Bd = Ad + A_BYTES;
        #pragma unroll
        for (int e = 0; e < 2; e++) {       // A: 128 rows x 128B = 1024 x 16B
            int j = tid + e * NTHR;
            int r = j >> 3, seg = j & 7;
            int gs = s0 + r + tap - 1;      // batch-local padded row
            bool ok = (unsigned)gs < (unsigned)SEQ;
            const void* src = ok ? (const void*)(Ain + (rowBase + gs) * CH + c0 + seg * 8)
                                 : (const void*)Ain;
            cp_async16(Ad + (r * APAD + seg * 8) * 2, src, ok ? 16 : 0);
        }
        #pragma unroll
        for (int e = 0; e < 6; e++) {       // B: 384 rows x 128B = 3072 x 16B
            int j = tid + e * NTHR;
            int n = j >> 3, seg = j & 7;
            cp_async16(Bd + (n * APAD + seg * 8) * 2,
                       WT + (size_t)n * KTOT + ci * KC + seg * 8);
        }
    };

    const int wid = tid >> 5, lane = tid & 31;
    const int wm = wid >> 2, wn = wid & 3;   // 4x4 warp grid; warp tile 32(M) x 96(N)

    const int aRow = wm * 32 + (lane & 7) + ((lane >> 3) & 1) * 8;
    const int aCol = (lane >> 4) * 8;                    // halves within k16 step
    const uint32_t aBase = (uint32_t)((aRow * APAD + aCol) * 2);
    const int bRow = wn * 96 + (lane & 7) + ((lane >> 4) & 1) * 8;
    const int bCol = ((lane >> 3) & 1) * 8;              // halves within k16 step
    const uint32_t bBase = (uint32_t)((bRow * APAD + bCol) * 2);

    float c[2][12][4];
    #pragma unroll
    for (int mt = 0; mt < 2; mt++)
        #pragma unroll
        for (int nt = 0; nt < 12; nt++)
            #pragma unroll
            for (int i = 0; i < 4; i++) c[mt][nt][i] = 0.0f;

    load_tile(0, 0); cp_commit();
    load_tile(1, 1); cp_commit();

    for (int ci = 0; ci < NITER; ci++) {
        const int st = ci % NSTAGE;
        if (ci < NITER - 1) cp_wait1(); else cp_wait0();
        __syncthreads();
        // issue next stage's loads now (overlaps with this iter's compute);
        // stage (ci+2)%3 == (ci-1)%3 was fully consumed before the barrier above.
        if (ci + 2 < NITER) { load_tile(ci + 2, (ci + 2) % NSTAGE); cp_commit(); }

        const uint32_t Asb = smem_base + st * STAGE_BYTES + aBase;
        const uint32_t Bsb = smem_base + st * STAGE_BYTES + A_BYTES + bBase;
        #pragma unroll
        for (int ks = 0; ks < 4; ks++) {     // 4 x k16 per KC=64 chunk
            uint32_t a[2][4];
            ldsm4(a[0], Asb + ks * 32);                       // rows wm*32 +  0..15
            ldsm4(a[1], Asb + 16 * APAD * 2 + ks * 32);       // rows wm*32 + 16..31
            #pragma unroll
            for (int np = 0; np < 6; np++) {
                uint32_t bb[4];                               // 2 n8 fragments
                ldsm4(bb, Bsb + np * 16 * APAD * 2 + ks * 32);
                mma16816(c[0][2*np  ], a[0], bb[0], bb[1]);
                mma16816(c[1][2*np  ], a[1], bb[0], bb[1]);
                mma16816(c[0][2*np+1], a[0], bb[2], bb[3]);
                mma16816(c[1][2*np+1], a[1], bb[2], bb[3]);
            }
        }
    }
    __syncthreads();    // mainloop done; stage-0 smem now reusable as epilogue scratch

    // ---- epilogue: +bias, LayerNorm stats ----
    const int g = lane >> 2, tg = lane & 3;
    float psum[2][2] = {{0,0},{0,0}}, psq[2][2] = {{0,0},{0,0}};
    #pragma unroll
    for (int mt = 0; mt < 2; mt++)
        #pragma unroll
        for (int nt = 0; nt < 12; nt++) {
            int col0 = wn * 96 + nt * 8 + tg * 2;
            float bb0 = sBias[col0], bb1 = sBias[col0 + 1];
            c[mt][nt][0] += bb0; c[mt][nt][1] += bb1;
            c[mt][nt][2] += bb0; c[mt][nt][3] += bb1;
            psum[mt][0] += c[mt][nt][0] + c[mt][nt][1];
            psq [mt][0] += c[mt][nt][0]*c[mt][nt][0] + c[mt][nt][1]*c[mt][nt][1];
            psum[mt][1] += c[mt][nt][2] + c[mt][nt][3];
            psq [mt][1] += c[mt][nt][2]*c[mt][nt][2] + c[mt][nt][3]*c[mt][nt][3];
        }
    #pragma unroll
    for (int mt = 0; mt < 2; mt++)
        #pragma unroll
        for (int hi = 0; hi < 2; hi++) {
            float s = psum[mt][hi], q = psq[mt][hi];
            s += __shfl_xor_sync(0xffffffffu, s, 1); s += __shfl_xor_sync(0xffffffffu, s, 2);
            q += __shfl_xor_sync(0xffffffffu, q, 1); q += __shfl_xor_sync(0xffffffffu, q, 2);
            if (tg == 0) {
                int r = wm * 32 + mt * 16 + g + 8 * hi;
                sPart[r * 8 + wn] = s;
                sPart[r * 8 + 4 + wn] = q;
            }
        }
    __syncthreads();
    if (tid < TM) {
        float s = sPart[tid*8+0] + sPart[tid*8+1] + sPart[tid*8+2] + sPart[tid*8+3];
        float q = sPart[tid*8+4] + sPart[tid*8+5] + sPart[tid*8+6] + sPart[tid*8+7];
        float mean = s * (1.0f / CH);
        float var  = q * (1.0f / CH) - mean * mean;
        sMean[tid] = mean;
        sRstd[tid] = rsqrtf(var + 1e-5f);
    }
    __syncthreads();

    // ---- normalize + relu; store bf16 OR fused linear+exp ----
    float pd[2][2] = {{0,0},{0,0}};
    #pragma unroll
    for (int mt = 0; mt < 2; mt++) {
        int r0 = wm * 32 + mt * 16 + g;
        float m0 = sMean[r0],   rs0 = sRstd[r0];
        float m1 = sMean[r0+8], rs1 = sRstd[r0+8];
        #pragma unroll
        for (int nt = 0; nt < 12; nt++) {
            int col0 = wn * 96 + nt * 8 + tg * 2;
            float ga0 = sGamma[col0], ga1 = sGamma[col0+1];
            float be0 = sBeta[col0],  be1 = sBeta[col0+1];
            float v0 = fmaxf(0.f, (c[mt][nt][0] - m0) * rs0 * ga0 + be0);
            float v1 = fmaxf(0.f, (c[mt][nt][1] - m0) * rs0 * ga1 + be1);
            float v2 = fmaxf(0.f, (c[mt][nt][2] - m1) * rs1 * ga0 + be0);
            float v3 = fmaxf(0.f, (c[mt][nt][3] - m1) * rs1 * ga1 + be1);
            if (!PRED) {
                size_t base0 = (rowBase + s0 + r0) * CH + col0;
                *(__nv_bfloat162*)(g_h1 + base0)          = __floats2bfloat162_rn(v0, v1);
                *(__nv_bfloat162*)(g_h1 + base0 + 8 * CH) = __floats2bfloat162_rn(v2, v3);
            } else {
                float w0 = sWl[col0], w1v = sWl[col0 + 1];
                pd[mt][0] += v0 * w0 + v1 * w1v;
                pd[mt][1] += v2 * w0 + v3 * w1v;
            }
        }
    }
    if (!PRED) {
        // publish h1 tile: order stores before flag (release)
        __syncthreads();
        __threadfence();
        if (tid == 0) *(volatile int*)&g_flag[bidx] = 1;
    } else {
        #pragma unroll
        for (int mt = 0; mt < 2; mt++)
            #pragma unroll
            for (int hi = 0; hi < 2; hi++) {
                float s = pd[mt][hi];
                s += __shfl_xor_sync(0xffffffffu, s, 1);
                s += __shfl_xor_sync(0xffffffffu, s, 2);
                if (tg == 0) {
                    int r = wm * 32 + mt * 16 + g + 8 * hi;
                    sPart[r * 8 + wn] = s;
                }
            }
        __syncthreads();
        if (tid < TM) {
            float s = sPart[tid*8+0] + sPart[tid*8+1] + sPart[tid*8+2] + sPart[tid*8+3];
            pred[rowBase + s0 + tid] = expf(s + bl[0]);
        }
    }
}

// ---------------- length regulation (exact gather of fp32 x) ----------------
__global__ void gather_kernel(const float* __restrict__ x, float* __restrict__ out) {
    __shared__ int sc[SEQ];
    int b = blockIdx.y;
    for (int i = threadIdx.x; i < SEQ; i += blockDim.x) sc[i] = g_cum[b * SEQ + i];
    __syncthreads();

    int warp = threadIdx.x >> 5, lane = threadIdx.x & 31;
    int t = blockIdx.x * 8 + warp;            // 0..3071
    int total = sc[SEQ - 1];
    bool valid = t < total;
    int lo = 0, hi = SEQ;
    while (lo < hi) { int mid = (lo + hi) >> 1; if (sc[mid] <= t) lo = mid + 1; else hi = mid; }
    int src = min(lo, SEQ - 1);

    const float4* xp = (const float4*)(x + ((size_t)b * SEQ + src) * CH);
    float4* op = (float4*)(out + ((size_t)b * MAXOUT + t) * CH);
    #pragma unroll
    for (int i = 0; i < 3; i++) {
        float4 v = valid ? xp[lane + 32 * i] : make_float4(0.f, 0.f, 0.f, 0.f);
        op[lane + 32 * i] = v;
    }
}

// ---------------- launch ----------------
extern "C" void kernel_launch(void* const* d_in, const int* in_sizes, int n_in,
                              void* d_out, int out_size) {
    const float* x     = (const float*)d_in[0];
    const int*   dur   = (const int*)  d_in[1];
    const float* w1    = (const float*)d_in[2];
    const float* b1    = (const float*)d_in[3];
    const float* g1    = (const float*)d_in[4];
    const float* beta1 = (const float*)d_in[5];
    const float* w2    = (const float*)d_in[6];
    const float* b2    = (const float*)d_in[7];
    const float* g2    = (const float*)d_in[8];
    const float* beta2 = (const float*)d_in[9];
    const float* wl    = (const float*)d_in[10];
    const float* bl    = (const float*)d_in[11];

    float* res  = (float*)d_out;
    float* pred = res + (size_t)BATCH * MAXOUT * CH;

    static cudaStream_t s_aux = nullptr;
    static cudaEvent_t  ev_fork = nullptr, ev_join = nullptr;
    static bool s_init = false;
    if (!s_init) {
        cudaStreamCreateWithFlags(&s_aux, cudaStreamNonBlocking);
        cudaEventCreateWithFlags(&ev_fork, cudaEventDisableTiming);
        cudaEventCreateWithFlags(&ev_join, cudaEventDisableTiming);
        cudaFuncSetAttribute(conv_ln_kernel, cudaFuncAttributeMaxDynamicSharedMemorySize, SMEM_TOTAL);
        s_init = true;
    }

    // ---- fork: aux branch = cumsum -> gather (memory-bound, independent of convs) ----
    cudaEventRecord(ev_fork, 0);
    cudaStreamWaitEvent(s_aux, ev_fork, 0);
    cumsum_kernel<<<BATCH, SEQ, 0, s_aux>>>(dur);
    gather_kernel<<<dim3(MAXOUT / 8, BATCH), 256, 0, s_aux>>>(x, res);
    cudaEventRecord(ev_join, s_aux);

    // ---- main branch: merged prep, then dual-layer pipelined conv ----
    prep_kernel<<<(PREP_TOTAL + 255) / 256, 256>>>(x, w1, w2);
    conv_ln_kernel<<<2 * NTILES, NTHR, SMEM_TOTAL>>>(b1, g1, beta1, b2, g2, beta2, wl, bl, pred);

    // ---- join ----
    cudaStreamWaitEvent(0, ev_join, 0);
}